// round 2
// baseline (speedup 1.0000x reference)
#include <cuda_runtime.h>
#include <math.h>

#define B_SAMP 8192
#define K_DIM  7056
#define N1     512
#define FEAT   256
#define NQ     8
#define NL     3

// scratch: h = relu(x @ W1 + b1)  [8192, 512]
__device__ float g_h[(size_t)B_SAMP * N1];
// precomputed gate trig: per (layer,qubit): cx,sx,cy,sy,cz,sz
__device__ float g_gate[NL * NQ * 6];

// ---------------------------------------------------------------------------
// Gate-parameter precompute (qparams are batch-independent)
// ---------------------------------------------------------------------------
__global__ void prep_gates_kernel(const float* __restrict__ qp) {
    int p = threadIdx.x;
    if (p < NL * NQ) {
        float hx = 0.5f * qp[p * 3 + 0];
        float hy = 0.5f * qp[p * 3 + 1];
        float hz = 0.5f * qp[p * 3 + 2];
        float cx, sx, cy, sy, cz, sz;
        sincosf(hx, &sx, &cx);
        sincosf(hy, &sy, &cy);
        sincosf(hz, &sz, &cz);
        g_gate[p * 6 + 0] = cx; g_gate[p * 6 + 1] = sx;
        g_gate[p * 6 + 2] = cy; g_gate[p * 6 + 3] = sy;
        g_gate[p * 6 + 4] = cz; g_gate[p * 6 + 5] = sz;
    }
}

// ---------------------------------------------------------------------------
// GEMM1: h = relu(x @ W1 + b1)   M=8192, K=7056, N=512 (fp32, SIMT baseline)
// 128x128 block tile, BK=8, 256 threads, 8x8 microtile, double-buffered smem
// ---------------------------------------------------------------------------
#define BM 128
#define BN 128
#define BK 8
#define APAD 132   // padded A-tile row to kill store bank conflicts

__global__ __launch_bounds__(256, 2) void gemm1_relu_kernel(
    const float* __restrict__ X, const float* __restrict__ W,
    const float* __restrict__ bias)
{
    __shared__ float As[2][BK][APAD];
    __shared__ float Bs[2][BK][BN];

    const int tid = threadIdx.x;
    const int m0 = blockIdx.y * BM;
    const int n0 = blockIdx.x * BN;

    // A loader: 128 rows x 8 cols -> 256 float4 (1 per thread)
    const int arow = tid >> 1;
    const int acol = (tid & 1) << 2;
    // B loader: 8 rows x 128 cols -> 256 float4 (1 per thread)
    const int brow = tid >> 5;
    const int bcol = (tid & 31) << 2;

    const float* Aptr = X + (size_t)(m0 + arow) * K_DIM + acol;
    const float* Bptr = W + (size_t)brow * N1 + n0 + bcol;

    float4 a4 = *(const float4*)(Aptr);
    float4 b4 = *(const float4*)(Bptr);
    As[0][acol + 0][arow] = a4.x;
    As[0][acol + 1][arow] = a4.y;
    As[0][acol + 2][arow] = a4.z;
    As[0][acol + 3][arow] = a4.w;
    *(float4*)&Bs[0][brow][bcol] = b4;
    __syncthreads();

    float acc[8][8];
    #pragma unroll
    for (int i = 0; i < 8; i++)
        #pragma unroll
        for (int j = 0; j < 8; j++) acc[i][j] = 0.0f;

    const int tx = (tid & 15) << 3;   // 0..120
    const int ty = (tid >> 4) << 3;   // 0..120

    const int nTiles = K_DIM / BK;    // 882
    for (int t = 0; t < nTiles; t++) {
        const int buf = t & 1;
        if (t + 1 < nTiles) {
            a4 = *(const float4*)(Aptr + (size_t)(t + 1) * BK);
            b4 = *(const float4*)(Bptr + (size_t)(t + 1) * BK * N1);
        }
        #pragma unroll
        for (int kk = 0; kk < BK; kk++) {
            float af[8], bf[8];
            *(float4*)&af[0] = *(const float4*)&As[buf][kk][ty];
            *(float4*)&af[4] = *(const float4*)&As[buf][kk][ty + 4];
            *(float4*)&bf[0] = *(const float4*)&Bs[buf][kk][tx];
            *(float4*)&bf[4] = *(const float4*)&Bs[buf][kk][tx + 4];
            #pragma unroll
            for (int i = 0; i < 8; i++)
                #pragma unroll
                for (int j = 0; j < 8; j++)
                    acc[i][j] = fmaf(af[i], bf[j], acc[i][j]);
        }
        if (t + 1 < nTiles) {
            const int nb = buf ^ 1;
            As[nb][acol + 0][arow] = a4.x;
            As[nb][acol + 1][arow] = a4.y;
            As[nb][acol + 2][arow] = a4.z;
            As[nb][acol + 3][arow] = a4.w;
            *(float4*)&Bs[nb][brow][bcol] = b4;
            __syncthreads();
        }
    }

    float bb[8];
    #pragma unroll
    for (int j = 0; j < 8; j++) bb[j] = bias[n0 + tx + j];

    #pragma unroll
    for (int i = 0; i < 8; i++) {
        size_t base = (size_t)(m0 + ty + i) * N1 + n0 + tx;
        float4 o0, o1;
        o0.x = fmaxf(acc[i][0] + bb[0], 0.f);
        o0.y = fmaxf(acc[i][1] + bb[1], 0.f);
        o0.z = fmaxf(acc[i][2] + bb[2], 0.f);
        o0.w = fmaxf(acc[i][3] + bb[3], 0.f);
        o1.x = fmaxf(acc[i][4] + bb[4], 0.f);
        o1.y = fmaxf(acc[i][5] + bb[5], 0.f);
        o1.z = fmaxf(acc[i][6] + bb[6], 0.f);
        o1.w = fmaxf(acc[i][7] + bb[7], 0.f);
        *(float4*)&g_h[base]     = o0;
        *(float4*)&g_h[base + 4] = o1;
    }
}

// ---------------------------------------------------------------------------
// Fused tail: angles (h @ W2[:, :8] + tanh) -> 8-qubit sim -> post-MLP
// One warp per sample. State: 8 complex amps per lane (global idx = lane*8+j;
// qubit w lives at index bit (7-w); bits 7..3 = lane bits 4..0, bits 2..0 = j)
// ---------------------------------------------------------------------------
__device__ __forceinline__ float bsum(float v) {
    #pragma unroll
    for (int m = 16; m > 0; m >>= 1) v += __shfl_xor_sync(0xffffffffu, v, m);
    return v;
}

__global__ __launch_bounds__(256) void tail_kernel(
    const float* __restrict__ preW2, const float* __restrict__ preb2,
    const float* __restrict__ pW1, const float* __restrict__ pb1,
    const float* __restrict__ pW2, const float* __restrict__ pb2,
    const float* __restrict__ pW3, const float* __restrict__ pb3,
    float* __restrict__ out)
{
    __shared__ float sh[8][128];      // per-warp hidden scratch
    __shared__ float w2s[128 * 64];   // post_W2 staged in smem (32 KB)

    const int lane = threadIdx.x & 31;
    const int w    = threadIdx.x >> 5;
    const int sample = blockIdx.x * 8 + w;

    // cooperative stage of post_W2
    for (int i = threadIdx.x; i < (128 * 64) / 4; i += 256)
        ((float4*)w2s)[i] = ((const float4*)pW2)[i];
    __syncthreads();

    // ---- angles: 8 dot products of length 512 over the warp ----
    const float* hrow = g_h + (size_t)sample * N1;
    float acc[8] = {0, 0, 0, 0, 0, 0, 0, 0};
    #pragma unroll
    for (int t = 0; t < 16; t++) {
        const int k = t * 32 + lane;
        const float hv = hrow[k];
        const float4 wa = *(const float4*)(preW2 + (size_t)k * FEAT);
        const float4 wb = *(const float4*)(preW2 + (size_t)k * FEAT + 4);
        acc[0] = fmaf(hv, wa.x, acc[0]); acc[1] = fmaf(hv, wa.y, acc[1]);
        acc[2] = fmaf(hv, wa.z, acc[2]); acc[3] = fmaf(hv, wa.w, acc[3]);
        acc[4] = fmaf(hv, wb.x, acc[4]); acc[5] = fmaf(hv, wb.y, acc[5]);
        acc[6] = fmaf(hv, wb.z, acc[6]); acc[7] = fmaf(hv, wb.w, acc[7]);
    }

    // ---- initial product state: per qubit, RY(θ)·H·|0> = ((c-s)/√2,(c+s)/√2)
    float v0[8], v1[8];
    #pragma unroll
    for (int q = 0; q < 8; q++) {
        const float s_ = bsum(acc[q]);
        const float th = tanhf(s_ + preb2[q]) * 1.57079632679f; // θ/2 = feat*π/2
        float c, s;
        sincosf(th, &s, &c);
        v0[q] = (c - s) * 0.70710678118f;
        v1[q] = (c + s) * 0.70710678118f;
    }
    float re[8], im[8];
    #pragma unroll
    for (int j = 0; j < 8; j++) {
        const int g = (lane << 3) | j;
        float a = 1.0f;
        #pragma unroll
        for (int q = 0; q < 8; q++)
            a *= ((g >> (7 - q)) & 1) ? v1[q] : v0[q];
        re[j] = a; im[j] = 0.0f;
    }

    // ---- entangling layers ----
    for (int l = 0; l < NL; l++) {
        // CNOT(0,1): ctrl lane-bit4, tgt lane-bit3
        {
            const int take = (lane >> 4) & 1;
            #pragma unroll
            for (int j = 0; j < 8; j++) {
                const float orr = __shfl_xor_sync(~0u, re[j], 8);
                const float oii = __shfl_xor_sync(~0u, im[j], 8);
                if (take) { re[j] = orr; im[j] = oii; }
            }
        }
        // CNOT(2,3): ctrl lane-bit2, tgt lane-bit1
        {
            const int take = (lane >> 2) & 1;
            #pragma unroll
            for (int j = 0; j < 8; j++) {
                const float orr = __shfl_xor_sync(~0u, re[j], 2);
                const float oii = __shfl_xor_sync(~0u, im[j], 2);
                if (take) { re[j] = orr; im[j] = oii; }
            }
        }
        // CNOT(4,5): ctrl lane-bit0, tgt j-bit2
        if (lane & 1) {
            #pragma unroll
            for (int j = 0; j < 4; j++) {
                float t = re[j]; re[j] = re[j + 4]; re[j + 4] = t;
                t = im[j]; im[j] = im[j + 4]; im[j + 4] = t;
            }
        }
        // CNOT(6,7): ctrl j-bit1, tgt j-bit0 -> swap (2,3),(6,7)
        {
            float t;
            t = re[2]; re[2] = re[3]; re[3] = t;  t = im[2]; im[2] = im[3]; im[3] = t;
            t = re[6]; re[6] = re[7]; re[7] = t;  t = im[6]; im[6] = im[7]; im[7] = t;
        }
        // CNOT(1,2): ctrl lane-bit3, tgt lane-bit2
        {
            const int take = (lane >> 3) & 1;
            #pragma unroll
            for (int j = 0; j < 8; j++) {
                const float orr = __shfl_xor_sync(~0u, re[j], 4);
                const float oii = __shfl_xor_sync(~0u, im[j], 4);
                if (take) { re[j] = orr; im[j] = oii; }
            }
        }
        // CNOT(3,4): ctrl lane-bit1, tgt lane-bit0
        {
            const int take = (lane >> 1) & 1;
            #pragma unroll
            for (int j = 0; j < 8; j++) {
                const float orr = __shfl_xor_sync(~0u, re[j], 1);
                const float oii = __shfl_xor_sync(~0u, im[j], 1);
                if (take) { re[j] = orr; im[j] = oii; }
            }
        }
        // CNOT(5,6): ctrl j-bit2, tgt j-bit1 -> swap (4,6),(5,7)
        {
            float t;
            t = re[4]; re[4] = re[6]; re[6] = t;  t = im[4]; im[4] = im[6]; im[6] = t;
            t = re[5]; re[5] = re[7]; re[7] = t;  t = im[5]; im[5] = im[7]; im[7] = t;
        }

        // per-qubit RX, RY, RZ
        #pragma unroll
        for (int q = 0; q < 8; q++) {
            const float* gg = g_gate + (l * 8 + q) * 6;
            const float cx = gg[0], sx = gg[1];
            const float cy = gg[2], sy = gg[3];
            const float cz = gg[4], szv = gg[5];
            if (q < 5) {
                const int M = 1 << (4 - q);
                const int bit = (lane >> (4 - q)) & 1;
                // RX: new = c*mine - i*s*other (role-independent)
                #pragma unroll
                for (int j = 0; j < 8; j++) {
                    const float orr = __shfl_xor_sync(~0u, re[j], M);
                    const float oii = __shfl_xor_sync(~0u, im[j], M);
                    const float nr = fmaf(sx, oii, cx * re[j]);
                    const float ni = fmaf(-sx, orr, cx * im[j]);
                    re[j] = nr; im[j] = ni;
                }
                // RY: new = c*mine + (bit ? +s : -s)*other
                const float sgn = bit ? sy : -sy;
                #pragma unroll
                for (int j = 0; j < 8; j++) {
                    const float orr = __shfl_xor_sync(~0u, re[j], M);
                    const float oii = __shfl_xor_sync(~0u, im[j], M);
                    re[j] = fmaf(sgn, orr, cy * re[j]);
                    im[j] = fmaf(sgn, oii, cy * im[j]);
                }
                // RZ: multiply by cz + i*(bit ? +sz : -sz)
                const float szb = bit ? szv : -szv;
                #pragma unroll
                for (int j = 0; j < 8; j++) {
                    const float nr = fmaf(-szb, im[j], cz * re[j]);
                    const float ni = fmaf(szb, re[j], cz * im[j]);
                    re[j] = nr; im[j] = ni;
                }
            } else {
                const int S = 1 << (7 - q); // 4, 2, 1
                #pragma unroll
                for (int j0 = 0; j0 < 8; j0++) {
                    if (j0 & S) continue;
                    const int j1 = j0 + S;
                    float r0 = re[j0], i0 = im[j0], r1 = re[j1], i1 = im[j1];
                    // RX
                    float nr0 = fmaf(sx, i1, cx * r0);
                    float ni0 = fmaf(-sx, r1, cx * i0);
                    float nr1 = fmaf(sx, i0, cx * r1);
                    float ni1 = fmaf(-sx, r0, cx * i1);
                    r0 = nr0; i0 = ni0; r1 = nr1; i1 = ni1;
                    // RY
                    nr0 = fmaf(-sy, r1, cy * r0);
                    ni0 = fmaf(-sy, i1, cy * i0);
                    nr1 = fmaf(sy, r0, cy * r1);
                    ni1 = fmaf(sy, i0, cy * i1);
                    r0 = nr0; i0 = ni0; r1 = nr1; i1 = ni1;
                    // RZ: a0 *= (cz - i sz); a1 *= (cz + i sz)
                    re[j0] = fmaf(szv, i0, cz * r0);
                    im[j0] = fmaf(-szv, r0, cz * i0);
                    re[j1] = fmaf(-szv, i1, cz * r1);
                    im[j1] = fmaf(szv, r1, cz * i1);
                }
            }
        }
    }

    // ---- expectation values ----
    float ev[8] = {0, 0, 0, 0, 0, 0, 0, 0};
    #pragma unroll
    for (int j = 0; j < 8; j++) {
        const float p = re[j] * re[j] + im[j] * im[j];
        const int g = (lane << 3) | j;
        #pragma unroll
        for (int q = 0; q < 8; q++)
            ev[q] += ((g >> (7 - q)) & 1) ? -p : p;
    }
    #pragma unroll
    for (int q = 0; q < 8; q++) ev[q] = bsum(ev[q]);

    // ---- post-MLP ----
    float* shw = sh[w];
    #pragma unroll
    for (int r = 0; r < 4; r++) {
        const int u = r * 32 + lane;
        float s_ = pb1[u];
        #pragma unroll
        for (int q = 0; q < 8; q++)
            s_ = fmaf(ev[q], pW1[q * 128 + u], s_);
        shw[u] = fmaxf(s_, 0.0f);
    }
    __syncwarp();

    // layer 2: each lane computes v = 2*lane, 2*lane+1 (float2 smem loads)
    float s0 = pb2[2 * lane], s1 = pb2[2 * lane + 1];
    #pragma unroll 4
    for (int u = 0; u < 128; u++) {
        const float hu = shw[u];
        const float2 wv = *(const float2*)&w2s[u * 64 + 2 * lane];
        s0 = fmaf(hu, wv.x, s0);
        s1 = fmaf(hu, wv.y, s1);
    }
    const float h3a = fmaxf(s0, 0.0f);
    const float h3b = fmaxf(s1, 0.0f);
    __syncwarp();
    shw[2 * lane] = h3a;
    shw[2 * lane + 1] = h3b;
    __syncwarp();

    if (lane < 6) {
        float s_ = pb3[lane];
        #pragma unroll 8
        for (int v = 0; v < 64; v++)
            s_ = fmaf(shw[v], pW3[v * 6 + lane], s_);
        out[(size_t)sample * 6 + lane] = s_;
    }
}

// ---------------------------------------------------------------------------
extern "C" void kernel_launch(void* const* d_in, const int* in_sizes, int n_in,
                              void* d_out, int out_size)
{
    const float* x     = (const float*)d_in[0];
    const float* preW1 = (const float*)d_in[1];
    const float* preb1 = (const float*)d_in[2];
    const float* preW2 = (const float*)d_in[3];
    const float* preb2 = (const float*)d_in[4];
    const float* qp    = (const float*)d_in[5];
    const float* pW1   = (const float*)d_in[6];
    const float* pb1   = (const float*)d_in[7];
    const float* pW2   = (const float*)d_in[8];
    const float* pb2   = (const float*)d_in[9];
    const float* pW3   = (const float*)d_in[10];
    const float* pb3   = (const float*)d_in[11];
    float* out = (float*)d_out;

    prep_gates_kernel<<<1, 32>>>(qp);

    dim3 g1(N1 / BN, B_SAMP / BM);   // (4, 64)
    gemm1_relu_kernel<<<g1, 256>>>(x, preW1, preb1);

    tail_kernel<<<B_SAMP / 8, 256>>>(preW2, preb2, pW1, pb1, pW2, pb2,
                                     pW3, pb3, out);
}

// round 5
// speedup vs baseline: 2.5271x; 2.5271x over previous
#include <cuda_runtime.h>
#include <cuda_bf16.h>
#include <stdint.h>
#include <math.h>

#define B_SAMP 8192
#define K_DIM  7056
#define KPAD   7104          // 111 * 64
#define N1     512
#define FEAT   256
#define NQ     8
#define NL     3

#define GBM 128
#define GBN 128
#define GKC 64
#define NCHUNK (KPAD / GKC)  // 111

// SMEM layout per buffer: A fp32 32KB | B_hi bf16 16KB | B_lo bf16 16KB
#define A_BYTES  32768
#define BH_OFF   32768
#define BL_OFF   49152
#define BUF_BYTES 65536
#define GSMEM (2 * BUF_BYTES)

// ---------------- device scratch ----------------
__device__ float g_h[(size_t)B_SAMP * N1];           // relu(x@W1+b1)
__device__ float g_gate[NL * NQ * 6];
__device__ __nv_bfloat16 g_wth[(size_t)N1 * KPAD];   // W1^T hi (K-major)
__device__ __nv_bfloat16 g_wtl[(size_t)N1 * KPAD];   // W1^T lo

// ---------------- helpers ----------------
__device__ __forceinline__ uint32_t smem_u32(const void* p) {
    uint32_t a;
    asm("{ .reg .u64 t; cvta.to.shared.u64 t, %1; cvt.u32.u64 %0, t; }"
        : "=r"(a) : "l"(p));
    return a;
}

__device__ __forceinline__ void cpasync16(uint32_t dst, const void* src, int bytes) {
    asm volatile("cp.async.cg.shared.global [%0], [%1], 16, %2;"
                 :: "r"(dst), "l"(src), "r"(bytes) : "memory");
}
__device__ __forceinline__ void cp_commit() {
    asm volatile("cp.async.commit_group;" ::: "memory");
}
__device__ __forceinline__ void cp_wait1() {
    asm volatile("cp.async.wait_group 1;" ::: "memory");
}
__device__ __forceinline__ void cp_wait0() {
    asm volatile("cp.async.wait_group 0;" ::: "memory");
}

__device__ __forceinline__ float2 lds64(uint32_t a) {
    float2 v;
    asm volatile("ld.shared.v2.f32 {%0,%1}, [%2];" : "=f"(v.x), "=f"(v.y) : "r"(a));
    return v;
}

__device__ __forceinline__ void ldsm4(uint32_t* r, uint32_t addr) {
    asm volatile("ldmatrix.sync.aligned.m8n8.x4.shared.b16 {%0,%1,%2,%3}, [%4];"
                 : "=r"(r[0]), "=r"(r[1]), "=r"(r[2]), "=r"(r[3]) : "r"(addr));
}

// pack 2 floats (e0 -> low 16 bits) to bf16x2
__device__ __forceinline__ uint32_t packbf(float e0, float e1) {
    uint32_t r;
    asm("cvt.rn.bf16x2.f32 %0, %1, %2;" : "=r"(r) : "f"(e1), "f"(e0));
    return r;
}
// residual (lo) pack given hi pair
__device__ __forceinline__ uint32_t packlo(uint32_t hpair, float e0, float e1) {
    float h0 = __uint_as_float(hpair << 16);
    float h1 = __uint_as_float(hpair & 0xFFFF0000u);
    return packbf(e0 - h0, e1 - h1);
}

__device__ __forceinline__ void mma_bf16(float* d, const uint32_t* a,
                                         uint32_t b0, uint32_t b1) {
    asm volatile(
        "mma.sync.aligned.m16n8k16.row.col.f32.bf16.bf16.f32 "
        "{%0,%1,%2,%3},{%4,%5,%6,%7},{%8,%9},{%0,%1,%2,%3};"
        : "+f"(d[0]), "+f"(d[1]), "+f"(d[2]), "+f"(d[3])
        : "r"(a[0]), "r"(a[1]), "r"(a[2]), "r"(a[3]), "r"(b0), "r"(b1));
}

// swizzles
__device__ __forceinline__ uint32_t swA(uint32_t off) {   // 256B rows (fp32 x64)
    return off ^ (((off >> 8) & 7) << 5);
}
__device__ __forceinline__ uint32_t swB(uint32_t off) {   // 128B rows (bf16 x64)
    return off ^ (((off >> 7) & 7) << 4);
}

// ---------------------------------------------------------------------------
// Gate-parameter precompute
// ---------------------------------------------------------------------------
__global__ void prep_gates_kernel(const float* __restrict__ qp) {
    int p = threadIdx.x;
    if (p < NL * NQ) {
        float cx, sx, cy, sy, cz, sz;
        sincosf(0.5f * qp[p * 3 + 0], &sx, &cx);
        sincosf(0.5f * qp[p * 3 + 1], &sy, &cy);
        sincosf(0.5f * qp[p * 3 + 2], &sz, &cz);
        g_gate[p * 6 + 0] = cx; g_gate[p * 6 + 1] = sx;
        g_gate[p * 6 + 2] = cy; g_gate[p * 6 + 3] = sy;
        g_gate[p * 6 + 4] = cz; g_gate[p * 6 + 5] = sz;
    }
}

// ---------------------------------------------------------------------------
// W1 split/transpose: g_wth/g_wtl[n][k] = bf16 hi/lo of W1[k][n], K padded
// ---------------------------------------------------------------------------
__global__ void wsplit_kernel(const float* __restrict__ W) {
    __shared__ float tile[32][33];
    const int k0 = blockIdx.x * 32;
    const int n0 = blockIdx.y * 32;
    const int tx = threadIdx.x, ty = threadIdx.y;  // 32 x 8
    #pragma unroll
    for (int i = 0; i < 4; i++) {
        const int k = k0 + ty + i * 8;
        tile[ty + i * 8][tx] = (k < K_DIM) ? W[(size_t)k * N1 + n0 + tx] : 0.0f;
    }
    __syncthreads();
    #pragma unroll
    for (int i = 0; i < 4; i++) {
        const int n = n0 + ty + i * 8;
        const float v = tile[tx][ty + i * 8];
        const __nv_bfloat16 h = __float2bfloat16(v);
        const float lo = v - __bfloat162float(h);
        g_wth[(size_t)n * KPAD + k0 + tx] = h;
        g_wtl[(size_t)n * KPAD + k0 + tx] = __float2bfloat16(lo);
    }
}

// ---------------------------------------------------------------------------
// GEMM1 via HMMA (mma.sync bf16, 3-term split, fp32 accum)
// CTA tile 128x128, KC=64, 8 warps (4m x 2n), warp tile 32x64
// A fp32 in smem via cp.async; split to bf16 during fragment build.
// B bf16 hi/lo in smem via cp.async; fragments via ldmatrix.x4.
// ---------------------------------------------------------------------------
__global__ __launch_bounds__(256, 1)
void gemm1_hmma_kernel(const float* __restrict__ X, const float* __restrict__ bias)
{
    extern __shared__ char smraw[];
    const uint32_t sb = smem_u32(smraw);

    const int tid  = threadIdx.x;
    const int lane = tid & 31;
    const int wid  = tid >> 5;
    const int wm   = wid >> 1;       // 0..3 -> m offset 32*wm
    const int wn   = wid & 1;        // 0..1 -> n offset 64*wn
    const int m0   = blockIdx.y * GBM;
    const int n0   = blockIdx.x * GBN;

    // ---- per-thread cp.async source/dest geometry ----
    // A: 8 chunks of 16B: idx = tid + 256*j; row = idx>>4 (0..127); g = idx&15
    // B: 4 chunks each for hi/lo: idx = tid + 256*j; n = idx>>3; g = idx&7
    uint32_t aDst[8]; const char* aSrc[8]; int aG[8];
    #pragma unroll
    for (int j = 0; j < 8; j++) {
        const int idx = tid + 256 * j;
        const int row = idx >> 4, g = idx & 15;
        aDst[j] = sb + swA(row * 256 + g * 16);
        aSrc[j] = (const char*)(X + (size_t)(m0 + row) * K_DIM + g * 4);
        aG[j] = g * 4;
    }
    uint32_t bDst[4]; const char *bhSrc[4], *blSrc[4];
    #pragma unroll
    for (int j = 0; j < 4; j++) {
        const int idx = tid + 256 * j;
        const int n = idx >> 3, g = idx & 7;
        bDst[j] = sb + swB(n * 128 + g * 16);
        bhSrc[j] = (const char*)(g_wth + (size_t)(n0 + n) * KPAD + g * 8);
        blSrc[j] = (const char*)(g_wtl + (size_t)(n0 + n) * KPAD + g * 8);
    }

    #define ISSUE(kb, buf) do {                                               \
        const uint32_t bo = (buf) * BUF_BYTES;                                \
        _Pragma("unroll")                                                     \
        for (int j = 0; j < 8; j++) {                                         \
            const int kc = (kb) + aG[j];                                      \
            const int bytes = (kc < K_DIM) ? 16 : 0;                          \
            const char* s = bytes ? aSrc[j] + (size_t)(kb) * 4 : (const char*)X; \
            cpasync16(aDst[j] + bo, s, bytes);                                \
        }                                                                     \
        _Pragma("unroll")                                                     \
        for (int j = 0; j < 4; j++) {                                         \
            cpasync16(bDst[j] + bo + BH_OFF, bhSrc[j] + (size_t)(kb) * 2, 16);\
            cpasync16(bDst[j] + bo + BL_OFF, blSrc[j] + (size_t)(kb) * 2, 16);\
        }                                                                     \
        cp_commit();                                                          \
    } while (0)

    float acc[2][8][4];
    #pragma unroll
    for (int i = 0; i < 2; i++)
        #pragma unroll
        for (int j = 0; j < 8; j++)
            #pragma unroll
            for (int c = 0; c < 4; c++) acc[i][j][c] = 0.0f;

    // fragment addressing (constant parts)
    const int fr = lane >> 2;        // fragment row within 8
    const int fc = (lane & 3) * 2;   // fragment col pair
    // B ldmatrix lane address pattern
    const int bgroup = lane >> 3;    // 0..3
    const int bwi = lane & 7;
    const int bsub = bgroup >> 1;        // which n-tile of the pair
    const int bkhalf = (bgroup & 1) * 8; // k offset 0/8

    ISSUE(0, 0);

    for (int t = 0; t < NCHUNK; t++) {
        const int buf = t & 1;
        if (t + 1 < NCHUNK) ISSUE((t + 1) * GKC, buf ^ 1);
        if (t + 1 < NCHUNK) cp_wait1(); else cp_wait0();
        __syncthreads();

        const uint32_t abase = sb + buf * BUF_BYTES;
        const uint32_t bhbase = abase + BH_OFF;
        const uint32_t blbase = abase + BL_OFF;

        #pragma unroll
        for (int kk = 0; kk < 4; kk++) {
            // ---- A fragments: LDS.64 fp32 + split to bf16 hi/lo ----
            uint32_t ah[2][4], al[2][4];
            #pragma unroll
            for (int mt = 0; mt < 2; mt++) {
                const int mrow = wm * 32 + mt * 16 + fr;
                const int kcol = kk * 16 + fc;
                const float2 v00 = lds64(abase + swA(mrow * 256 + kcol * 4));
                const float2 v10 = lds64(abase + swA((mrow + 8) * 256 + kcol * 4));
                const float2 v01 = lds64(abase + swA(mrow * 256 + (kcol + 8) * 4));
                const float2 v11 = lds64(abase + swA((mrow + 8) * 256 + (kcol + 8) * 4));
                ah[mt][0] = packbf(v00.x, v00.y);  al[mt][0] = packlo(ah[mt][0], v00.x, v00.y);
                ah[mt][1] = packbf(v10.x, v10.y);  al[mt][1] = packlo(ah[mt][1], v10.x, v10.y);
                ah[mt][2] = packbf(v01.x, v01.y);  al[mt][2] = packlo(ah[mt][2], v01.x, v01.y);
                ah[mt][3] = packbf(v11.x, v11.y);  al[mt][3] = packlo(ah[mt][3], v11.x, v11.y);
            }
            // ---- B fragments (pairs of n-tiles) + MMA ----
            #pragma unroll
            for (int p = 0; p < 4; p++) {
                const int ntile = p * 2 + bsub;
                const int n = wn * 64 + ntile * 8 + bwi;
                const int ke = kk * 16 + bkhalf;
                const uint32_t boff = swB(n * 128 + ke * 2);
                uint32_t bh[4], bl[4];
                ldsm4(bh, bhbase + boff);
                ldsm4(bl, blbase + boff);
                #pragma unroll
                for (int mt = 0; mt < 2; mt++) {
                    mma_bf16(acc[mt][2 * p],     ah[mt], bh[0], bh[1]);
                    mma_bf16(acc[mt][2 * p],     al[mt], bh[0], bh[1]);
                    mma_bf16(acc[mt][2 * p],     ah[mt], bl[0], bl[1]);
                    mma_bf16(acc[mt][2 * p + 1], ah[mt], bh[2], bh[3]);
                    mma_bf16(acc[mt][2 * p + 1], al[mt], bh[2], bh[3]);
                    mma_bf16(acc[mt][2 * p + 1], ah[mt], bl[2], bl[3]);
                }
            }
        }
        __syncthreads();
    }

    // ---- epilogue: bias + relu, float2 stores ----
    #pragma unroll
    for (int nt = 0; nt < 8; nt++) {
        const int c = n0 + wn * 64 + nt * 8 + fc;
        const float b0 = bias[c], b1 = bias[c + 1];
        #pragma unroll
        for (int mt = 0; mt < 2; mt++) {
            const int r = m0 + wm * 32 + mt * 16 + fr;
            float2 o0, o1;
            o0.x = fmaxf(acc[mt][nt][0] + b0, 0.f);
            o0.y = fmaxf(acc[mt][nt][1] + b1, 0.f);
            o1.x = fmaxf(acc[mt][nt][2] + b0, 0.f);
            o1.y = fmaxf(acc[mt][nt][3] + b1, 0.f);
            *(float2*)&g_h[(size_t)r * N1 + c] = o0;
            *(float2*)&g_h[(size_t)(r + 8) * N1 + c] = o1;
        }
    }
    #undef ISSUE
}

// ---------------------------------------------------------------------------
// Fused tail: angles -> 8-qubit sim -> post-MLP (one warp per sample)
// ---------------------------------------------------------------------------
__device__ __forceinline__ float bsum(float v) {
    #pragma unroll
    for (int m = 16; m > 0; m >>= 1) v += __shfl_xor_sync(0xffffffffu, v, m);
    return v;
}

__global__ __launch_bounds__(256) void tail_kernel(
    const float* __restrict__ preW2, const float* __restrict__ preb2,
    const float* __restrict__ pW1, const float* __restrict__ pb1,
    const float* __restrict__ pW2, const float* __restrict__ pb2,
    const float* __restrict__ pW3, const float* __restrict__ pb3,
    float* __restrict__ out)
{
    __shared__ float sh[8][128];
    __shared__ float w2s[128 * 64];

    const int lane = threadIdx.x & 31;
    const int w    = threadIdx.x >> 5;
    const int sample = blockIdx.x * 8 + w;

    for (int i = threadIdx.x; i < (128 * 64) / 4; i += 256)
        ((float4*)w2s)[i] = ((const float4*)pW2)[i];
    __syncthreads();

    const float* hrow = g_h + (size_t)sample * N1;
    float acc[8] = {0, 0, 0, 0, 0, 0, 0, 0};
    #pragma unroll
    for (int t = 0; t < 16; t++) {
        const int k = t * 32 + lane;
        const float hv = hrow[k];
        const float4 wa = *(const float4*)(preW2 + (size_t)k * FEAT);
        const float4 wb = *(const float4*)(preW2 + (size_t)k * FEAT + 4);
        acc[0] = fmaf(hv, wa.x, acc[0]); acc[1] = fmaf(hv, wa.y, acc[1]);
        acc[2] = fmaf(hv, wa.z, acc[2]); acc[3] = fmaf(hv, wa.w, acc[3]);
        acc[4] = fmaf(hv, wb.x, acc[4]); acc[5] = fmaf(hv, wb.y, acc[5]);
        acc[6] = fmaf(hv, wb.z, acc[6]); acc[7] = fmaf(hv, wb.w, acc[7]);
    }

    float v0[8], v1[8];
    #pragma unroll
    for (int q = 0; q < 8; q++) {
        const float s_ = bsum(acc[q]);
        const float th = tanhf(s_ + preb2[q]) * 1.57079632679f;
        float c, s;
        sincosf(th, &s, &c);
        v0[q] = (c - s) * 0.70710678118f;
        v1[q] = (c + s) * 0.70710678118f;
    }
    float re[8], im[8];
    #pragma unroll
    for (int j = 0; j < 8; j++) {
        const int g = (lane << 3) | j;
        float a = 1.0f;
        #pragma unroll
        for (int q = 0; q < 8; q++)
            a *= ((g >> (7 - q)) & 1) ? v1[q] : v0[q];
        re[j] = a; im[j] = 0.0f;
    }

    for (int l = 0; l < NL; l++) {
        {
            const int take = (lane >> 4) & 1;
            #pragma unroll
            for (int j = 0; j < 8; j++) {
                const float orr = __shfl_xor_sync(~0u, re[j], 8);
                const float oii = __shfl_xor_sync(~0u, im[j], 8);
                if (take) { re[j] = orr; im[j] = oii; }
            }
        }
        {
            const int take = (lane >> 2) & 1;
            #pragma unroll
            for (int j = 0; j < 8; j++) {
                const float orr = __shfl_xor_sync(~0u, re[j], 2);
                const float oii = __shfl_xor_sync(~0u, im[j], 2);
                if (take) { re[j] = orr; im[j] = oii; }
            }
        }
        if (lane & 1) {
            #pragma unroll
            for (int j = 0; j < 4; j++) {
                float t = re[j]; re[j] = re[j + 4]; re[j + 4] = t;
                t = im[j]; im[j] = im[j + 4]; im[j + 4] = t;
            }
        }
        {
            float t;
            t = re[2]; re[2] = re[3]; re[3] = t;  t = im[2]; im[2] = im[3]; im[3] = t;
            t = re[6]; re[6] = re[7]; re[7] = t;  t = im[6]; im[6] = im[7]; im[7] = t;
        }
        {
            const int take = (lane >> 3) & 1;
            #pragma unroll
            for (int j = 0; j < 8; j++) {
                const float orr = __shfl_xor_sync(~0u, re[j], 4);
                const float oii = __shfl_xor_sync(~0u, im[j], 4);
                if (take) { re[j] = orr; im[j] = oii; }
            }
        }
        {
            const int take = (lane >> 1) & 1;
            #pragma unroll
            for (int j = 0; j < 8; j++) {
                const float orr = __shfl_xor_sync(~0u, re[j], 1);
                const float oii = __shfl_xor_sync(~0u, im[j], 1);
                if (take) { re[j] = orr; im[j] = oii; }
            }
        }
        {
            float t;
            t = re[4]; re[4] = re[6]; re[6] = t;  t = im[4]; im[4] = im[6]; im[6] = t;
            t = re[5]; re[5] = re[7]; re[7] = t;  t = im[5]; im[5] = im[7]; im[7] = t;
        }

        #pragma unroll
        for (int q = 0; q < 8; q++) {
            const float* gg = g_gate + (l * 8 + q) * 6;
            const float cx = gg[0], sx = gg[1];
            const float cy = gg[2], sy = gg[3];
            const float cz = gg[4], szv = gg[5];
            if (q < 5) {
                const int M = 1 << (4 - q);
                const int bit = (lane >> (4 - q)) & 1;
                #pragma unroll
                for (int j = 0; j < 8; j++) {
                    const float orr = __shfl_xor_sync(~0u, re[j], M);
                    const float oii = __shfl_xor_sync(~0u, im[j], M);
                    const float nr = fmaf(sx, oii, cx * re[j]);
                    const float ni = fmaf(-sx, orr, cx * im[j]);
                    re[j] = nr; im[j] = ni;
                }
                const float sgn = bit ? sy : -sy;
                #pragma unroll
                for (int j = 0; j < 8; j++) {
                    const float orr = __shfl_xor_sync(~0u, re[j], M);
                    const float oii = __shfl_xor_sync(~0u, im[j], M);
                    re[j] = fmaf(sgn, orr, cy * re[j]);
                    im[j] = fmaf(sgn, oii, cy * im[j]);
                }
                const float szb = bit ? szv : -szv;
                #pragma unroll
                for (int j = 0; j < 8; j++) {
                    const float nr = fmaf(-szb, im[j], cz * re[j]);
                    const float ni = fmaf(szb, re[j], cz * im[j]);
                    re[j] = nr; im[j] = ni;
                }
            } else {
                const int S = 1 << (7 - q);
                #pragma unroll
                for (int j0 = 0; j0 < 8; j0++) {
                    if (j0 & S) continue;
                    const int j1 = j0 + S;
                    float r0 = re[j0], i0 = im[j0], r1 = re[j1], i1 = im[j1];
                    float nr0 = fmaf(sx, i1, cx * r0);
                    float ni0 = fmaf(-sx, r1, cx * i0);
                    float nr1 = fmaf(sx, i0, cx * r1);
                    float ni1 = fmaf(-sx, r0, cx * i1);
                    r0 = nr0; i0 = ni0; r1 = nr1; i1 = ni1;
                    nr0 = fmaf(-sy, r1, cy * r0);
                    ni0 = fmaf(-sy, i1, cy * i0);
                    nr1 = fmaf(sy, r0, cy * r1);
                    ni1 = fmaf(sy, i0, cy * i1);
                    r0 = nr0; i0 = ni0; r1 = nr1; i1 = ni1;
                    re[j0] = fmaf(szv, i0, cz * r0);
                    im[j0] = fmaf(-szv, r0, cz * i0);
                    re[j1] = fmaf(-szv, i1, cz * r1);
                    im[j1] = fmaf(szv, r1, cz * i1);
                }
            }
        }
    }

    float ev[8] = {0, 0, 0, 0, 0, 0, 0, 0};
    #pragma unroll
    for (int j = 0; j < 8; j++) {
        const float p = re[j] * re[j] + im[j] * im[j];
        const int g = (lane << 3) | j;
        #pragma unroll
        for (int q = 0; q < 8; q++)
            ev[q] += ((g >> (7 - q)) & 1) ? -p : p;
    }
    #pragma unroll
    for (int q = 0; q < 8; q++) ev[q] = bsum(ev[q]);

    float* shw = sh[w];
    #pragma unroll
    for (int r = 0; r < 4; r++) {
        const int u = r * 32 + lane;
        float s_ = pb1[u];
        #pragma unroll
        for (int q = 0; q < 8; q++)
            s_ = fmaf(ev[q], pW1[q * 128 + u], s_);
        shw[u] = fmaxf(s_, 0.0f);
    }
    __syncwarp();

    float s0 = pb2[2 * lane], s1 = pb2[2 * lane + 1];
    #pragma unroll 4
    for (int u = 0; u < 128; u++) {
        const float hu = shw[u];
        const float2 wv = *(const float2*)&w2s[u * 64 + 2 * lane];
        s0 = fmaf(hu, wv.x, s0);
        s1 = fmaf(hu, wv.y, s1);
    }
    const float h3a = fmaxf(s0, 0.0f);
    const float h3b = fmaxf(s1, 0.0f);
    __syncwarp();
    shw[2 * lane] = h3a;
    shw[2 * lane + 1] = h3b;
    __syncwarp();

    if (lane < 6) {
        float s_ = pb3[lane];
        #pragma unroll 8
        for (int v = 0; v < 64; v++)
            s_ = fmaf(shw[v], pW3[v * 6 + lane], s_);
        out[(size_t)sample * 6 + lane] = s_;
    }
}

// ---------------------------------------------------------------------------
extern "C" void kernel_launch(void* const* d_in, const int* in_sizes, int n_in,
                              void* d_out, int out_size)
{
    const float* x     = (const float*)d_in[0];
    const float* preW1 = (const float*)d_in[1];
    const float* preb1 = (const float*)d_in[2];
    const float* preW2 = (const float*)d_in[3];
    const float* preb2 = (const float*)d_in[4];
    const float* qp    = (const float*)d_in[5];
    const float* pW1   = (const float*)d_in[6];
    const float* pb1   = (const float*)d_in[7];
    const float* pW2   = (const float*)d_in[8];
    const float* pb2   = (const float*)d_in[9];
    const float* pW3   = (const float*)d_in[10];
    const float* pb3   = (const float*)d_in[11];
    float* out = (float*)d_out;

    cudaFuncSetAttribute(gemm1_hmma_kernel,
                         cudaFuncAttributeMaxDynamicSharedMemorySize, GSMEM);

    prep_gates_kernel<<<1, 32>>>(qp);
    wsplit_kernel<<<dim3(KPAD / 32, N1 / 32), dim3(32, 8)>>>(preW1);

    dim3 gg(N1 / GBN, B_SAMP / GBM);   // (4, 64)
    gemm1_hmma_kernel<<<gg, 256, GSMEM>>>(x, preb1);

    tail_kernel<<<B_SAMP / 8, 256>>>(preW2, preb2, pW1, pb1, pW2, pb2,
                                     pW3, pb3, out);
}